// round 12
// baseline (speedup 1.0000x reference)
#include <cuda_runtime.h>
#include <math.h>

// Problem constants
#define BQ   128
#define TQ   256
#define INQ  128
#define HQ   1024
#define NCTA 128      // 32 col-tiles x 4 K-splits; all co-resident
#define NTHR 256

#define TILEA 8192u   // int8 A tile: 128 rows x 32 k x (hi+lo planes) = 64B/row
#define TILEW 8192u   // int8 W tile: 128 rows x 32 k x (hi+lo)
#define STAGEB 16384u
#define NBUF 8        // whole phase prefetched

// Quantization (decoupled scales):
//  h = q_h / 32256           (|h| < 1)
//  x = q_x / 4032            (|x| <= 8)
//  W = q_w / 1032192         (|W| <= 1/32)
//  q = hi*256 + lo (int8 pair); products: acc_hh*65536 + acc_cross*256 (ll dropped)
//  Recurrent scale  S  = 1/(32256*1032192)
//  x-GEMM scale     Sx = 1/(4032*1032192)

// ---------------------------------------------------------------------------
// Device globals. Tiles contiguous + pre-swizzled. Row r = 64 bytes: 4 segs of
// 16B; logical seg = plane*2 + (k>>4); physical = logical ^ ((r>>1)&3).
// ---------------------------------------------------------------------------
__device__ __align__(1024) unsigned char g_Wxt[32u * 4u  * TILEW];  // W_ih0
__device__ __align__(1024) unsigned char g_W0t[32u * 32u * TILEW];  // W_hh0
__device__ __align__(1024) unsigned char g_W1t[32u * 64u * TILEW];  // W_ih1|W_hh1
__device__ __align__(1024) unsigned char g_xt[(unsigned)TQ * 4u * TILEA];
__device__ __align__(1024) unsigned char g_h0t[32u * TILEA];
__device__ __align__(1024) unsigned char g_h1t[32u * TILEA];
__device__ float g_xg[(size_t)TQ * BQ * 4096];   // 512MB: x @ W_ih0^T, [t][b][4H]
__device__ float g_h1f[BQ * HQ];
__device__ float g_c0[BQ * HQ];
__device__ float g_c1[BQ * HQ];
// Partial gate sums: layer0 4 slots, layer1 8 slots: [slot*32+tile][b][c]
__device__ float g_part0[4u * 32u * 128u * 128u];
__device__ float g_part1[8u * 32u * 128u * 128u];

__device__ unsigned g_bar_count = 0;
__device__ unsigned g_bar_gen   = 0;

__device__ __forceinline__ unsigned off8(int r, int k, int plane) {
    return (unsigned)(r * 64
        + ((((plane << 1) | (k >> 4)) ^ ((r >> 1) & 3)) << 4) + (k & 15));
}

// ---------------------------------------------------------------------------
// PTX helpers (sm_80/90 baseline — no 'a'-gated features)
// ---------------------------------------------------------------------------
__device__ __forceinline__ unsigned smem_u32(const void* p) {
    unsigned a;
    asm("{ .reg .u64 t; cvta.to.shared.u64 t, %1; cvt.u32.u64 %0, t; }"
        : "=r"(a) : "l"(p));
    return a;
}
__device__ __forceinline__ void mbar_init(unsigned mbar, unsigned cnt) {
    asm volatile("mbarrier.init.shared.b64 [%0], %1;" :: "r"(mbar), "r"(cnt) : "memory");
}
__device__ __forceinline__ void mbar_wait(unsigned mbar, unsigned parity) {
    asm volatile(
        "{\n\t.reg .pred P;\n\t"
        "W_%=:\n\t"
        "mbarrier.try_wait.parity.acquire.cta.shared::cta.b64 P, [%0], %1, 0x989680;\n\t"
        "@!P bra W_%=;\n\t}"
        :: "r"(mbar), "r"(parity) : "memory");
}
__device__ __forceinline__ void mbar_expect_tx(unsigned mbar, unsigned bytes) {
    asm volatile("mbarrier.arrive.expect_tx.shared.b64 _, [%0], %1;"
                 :: "r"(mbar), "r"(bytes) : "memory");
}
__device__ __forceinline__ void bulk_g2s(unsigned dst, const void* src,
                                         unsigned bytes, unsigned mbar) {
    asm volatile(
        "cp.async.bulk.shared::cluster.global.mbarrier::complete_tx::bytes "
        "[%0], [%1], %2, [%3];"
        :: "r"(dst), "l"(src), "r"(bytes), "r"(mbar) : "memory");
}
__device__ __forceinline__ void fence_async() {
    asm volatile("fence.proxy.async.shared::cta;" ::: "memory");
}
__device__ __forceinline__ void ldsm4(unsigned& r0, unsigned& r1,
                                      unsigned& r2, unsigned& r3, unsigned a) {
    asm volatile("ldmatrix.sync.aligned.m8n8.x4.shared.b16 {%0,%1,%2,%3}, [%4];"
                 : "=r"(r0), "=r"(r1), "=r"(r2), "=r"(r3) : "r"(a));
}
__device__ __forceinline__ void mma_s8(int* d, const unsigned* a, const unsigned* b) {
    asm volatile(
        "mma.sync.aligned.m16n8k32.row.col.s32.s8.s8.s32 "
        "{%0,%1,%2,%3}, {%4,%5,%6,%7}, {%8,%9}, {%0,%1,%2,%3};"
        : "+r"(d[0]), "+r"(d[1]), "+r"(d[2]), "+r"(d[3])
        : "r"(a[0]), "r"(a[1]), "r"(a[2]), "r"(a[3]), "r"(b[0]), "r"(b[1]));
}

// ---------------------------------------------------------------------------
// Grid barrier (all NCTA CTAs co-resident)
// ---------------------------------------------------------------------------
__device__ __forceinline__ void grid_bar() {
    __syncthreads();
    if (threadIdx.x == 0) {
        __threadfence();
        unsigned my = *(volatile unsigned*)&g_bar_gen;
        if (atomicAdd(&g_bar_count, 1u) == NCTA - 1u) {
            *(volatile unsigned*)&g_bar_count = 0;
            __threadfence();
            atomicExch(&g_bar_gen, my + 1u);
        } else {
            while (*(volatile unsigned*)&g_bar_gen == my) { }
        }
        __threadfence();
    }
    __syncthreads();
}

// ---------------------------------------------------------------------------
// Quantize + split helper
// ---------------------------------------------------------------------------
__device__ __forceinline__ void q_split(int q, int& hi, int& lo) {
    hi = (q + 128) >> 8;
    lo = q - (hi << 8);
}

// ---------------------------------------------------------------------------
// Init kernels (per replay; deterministic)
// ---------------------------------------------------------------------------
__global__ void init_state_kernel() {
    int i = blockIdx.x * blockDim.x + threadIdx.x;
    if (i < (int)(32 * TILEA / 4)) {
        ((unsigned*)g_h0t)[i] = 0u;
        ((unsigned*)g_h1t)[i] = 0u;
    }
    if (i < BQ * HQ) { g_c0[i] = 0.f; g_c1[i] = 0.f; }
}
__global__ void init_x_kernel(const float* __restrict__ x) {
    int i = blockIdx.x * blockDim.x + threadIdx.x;   // = b*32768 + t*128 + k
    if (i >= BQ * TQ * INQ) return;
    int k = i & 127, t = (i >> 7) & 255, b = i >> 15;
    int u = k >> 5, kl = k & 31;
    float v = x[i] * 4032.0f;
    v = fminf(fmaxf(v, -32256.f), 32256.f);
    int hi, lo; q_split(__float2int_rn(v), hi, lo);
    unsigned char* tb = g_xt + (size_t)(t * 4 + u) * TILEA;
    tb[off8(b, kl, 0)] = (unsigned char)hi;
    tb[off8(b, kl, 1)] = (unsigned char)lo;
}
__global__ void init_w_kernel(
    const float* __restrict__ W_ih0, const float* __restrict__ W_hh0,
    const float* __restrict__ W_ih1, const float* __restrict__ W_hh1)
{
    const unsigned NX = 32u * 4u  * 4096u;
    const unsigned N0 = 32u * 32u * 4096u;
    const unsigned N1 = 32u * 64u * 4096u;
    for (unsigned i = blockIdx.x * blockDim.x + threadIdx.x; i < NX + N0 + N1;
         i += gridDim.x * blockDim.x) {
        float v; unsigned char* dst; int r, kl;
        if (i < NX) {
            kl = (int)(i & 31u); r = (int)((i >> 5) & 127u);
            unsigned rest = i >> 12, u = rest & 3u, tile = rest >> 2;
            unsigned gcol = (((unsigned)r >> 5) << 10) + tile * 32u + ((unsigned)r & 31u);
            unsigned k = u * 32u + (unsigned)kl;                   // < 128
            v = W_ih0[(size_t)gcol * 128u + k];
            dst = g_Wxt + (size_t)(tile * 4u + u) * TILEW;
        } else if (i < NX + N0) {
            unsigned j = i - NX;
            kl = (int)(j & 31u); r = (int)((j >> 5) & 127u);
            unsigned rest = j >> 12, u = rest & 31u, tile = rest >> 5;
            unsigned gcol = (((unsigned)r >> 5) << 10) + tile * 32u + ((unsigned)r & 31u);
            unsigned k = u * 32u + (unsigned)kl;                   // < 1024
            v = W_hh0[(size_t)gcol * 1024u + k];
            dst = g_W0t + (size_t)(tile * 32u + u) * TILEW;
        } else {
            unsigned j = i - NX - N0;
            kl = (int)(j & 31u); r = (int)((j >> 5) & 127u);
            unsigned rest = j >> 12, u = rest & 63u, tile = rest >> 6;
            unsigned gcol = (((unsigned)r >> 5) << 10) + tile * 32u + ((unsigned)r & 31u);
            unsigned k = u * 32u + (unsigned)kl;
            v = (k < 1024u) ? W_ih1[(size_t)gcol * 1024u + k]
                            : W_hh1[(size_t)gcol * 1024u + (k - 1024u)];
            dst = g_W1t + (size_t)(tile * 64u + u) * TILEW;
        }
        float q = v * 1032192.0f;
        q = fminf(fmaxf(q, -32256.f), 32256.f);
        int hi, lo; q_split(__float2int_rn(q), hi, lo);
        dst[off8(r, kl, 0)] = (unsigned char)hi;
        dst[off8(r, kl, 1)] = (unsigned char)lo;
    }
}

// ---------------------------------------------------------------------------
// x-GEMM kernel (one-time per replay): g_xg[t][b][:] = x_t @ W_ih0^T
// Grid (32 tiles, 256 t), 256 threads, 8 warps 2Mx4N, K = 128 = 4 units.
// ---------------------------------------------------------------------------
__global__ __launch_bounds__(256) void xgemm_kernel() {
    extern __shared__ __align__(1024) unsigned char xsm[];
    const unsigned sb = smem_u32(xsm);
    const int tid  = threadIdx.x;
    const int lane = tid & 31;
    const int wid  = tid >> 5;
    const int wm   = wid >> 2;
    const int wn   = wid & 3;
    const int tile = blockIdx.x;
    const int t    = blockIdx.y;

    if (tid == 0) { mbar_init(sb, 1); fence_async(); }
    __syncthreads();
    if (tid == 0) {
        mbar_expect_tx(sb, 4u * STAGEB);
        #pragma unroll
        for (int u = 0; u < 4; ++u) {
            unsigned dst = sb + 1024u + (unsigned)u * STAGEB;
            bulk_g2s(dst,         g_xt  + (size_t)(t * 4 + u) * TILEA,    TILEA, sb);
            bulk_g2s(dst + TILEA, g_Wxt + (size_t)(tile * 4 + u) * TILEW, TILEW, sb);
        }
    }

    int acc_hh[4][4][4], acc_x[4][4][4];
    #pragma unroll
    for (int m = 0; m < 4; ++m)
        #pragma unroll
        for (int n = 0; n < 4; ++n)
            #pragma unroll
            for (int r = 0; r < 4; ++r) { acc_hh[m][n][r] = 0; acc_x[m][n][r] = 0; }

    mbar_wait(sb, 0);

    #pragma unroll
    for (int u = 0; u < 4; ++u) {
        unsigned bA = sb + 1024u + (unsigned)u * STAGEB;
        unsigned bW = bA + TILEA;

        unsigned AH[4][4], AL[4][4];
        #pragma unroll
        for (int m = 0; m < 4; ++m) {
            int row = wm * 64 + m * 16 + (lane & 15);
            unsigned rb = bA + (unsigned)(row * 64);
            unsigned sw = (unsigned)((row >> 1) & 3);
            ldsm4(AH[m][0], AH[m][1], AH[m][2], AH[m][3],
                  rb + (((unsigned)(lane >> 4) ^ sw) << 4));
            ldsm4(AL[m][0], AL[m][1], AL[m][2], AL[m][3],
                  rb + (((unsigned)(2 + (lane >> 4)) ^ sw) << 4));
        }
        unsigned WH[4][2], WL[4][2];
        #pragma unroll
        for (int np = 0; np < 2; ++np) {
            int nn = np * 2 + (lane >> 4);
            int rW = wn * 32 + nn * 8 + (lane & 7);
            unsigned rb = bW + (unsigned)(rW * 64);
            unsigned sw = (unsigned)((rW >> 1) & 3);
            unsigned half = (unsigned)((lane >> 3) & 1);
            ldsm4(WH[np*2][0], WH[np*2][1], WH[np*2+1][0], WH[np*2+1][1],
                  rb + ((half ^ sw) << 4));
            ldsm4(WL[np*2][0], WL[np*2][1], WL[np*2+1][0], WL[np*2+1][1],
                  rb + (((2u + half) ^ sw) << 4));
        }
        #pragma unroll
        for (int m = 0; m < 4; ++m)
            #pragma unroll
            for (int n = 0; n < 4; ++n)
                mma_s8(acc_hh[m][n], AH[m], WH[n]);
        #pragma unroll
        for (int m = 0; m < 4; ++m)
            #pragma unroll
            for (int n = 0; n < 4; ++n)
                mma_s8(acc_x[m][n], AH[m], WL[n]);
        #pragma unroll
        for (int m = 0; m < 4; ++m)
            #pragma unroll
            for (int n = 0; n < 4; ++n)
                mma_s8(acc_x[m][n], AL[m], WH[n]);
    }

    const float cx1 = (float)(65536.0 / (4032.0 * 1032192.0));
    const float cx2 = (float)(256.0   / (4032.0 * 1032192.0));
    float* xgt = g_xg + (size_t)t * (BQ * 4096);
    #pragma unroll
    for (int m = 0; m < 4; ++m)
        #pragma unroll
        for (int n = 0; n < 4; ++n) {
            int b = wm * 64 + m * 16 + (lane >> 2);
            int c = wn * 32 + n * 8 + (lane & 3) * 2;        // 0..127
            size_t col = (size_t)(c >> 5) * 1024 + tile * 32 + (c & 31);
            float f0 = __int2float_rn(acc_hh[m][n][0]) * cx1
                     + __int2float_rn(acc_x[m][n][0])  * cx2;
            float f1 = __int2float_rn(acc_hh[m][n][1]) * cx1
                     + __int2float_rn(acc_x[m][n][1])  * cx2;
            float f2 = __int2float_rn(acc_hh[m][n][2]) * cx1
                     + __int2float_rn(acc_x[m][n][2])  * cx2;
            float f3 = __int2float_rn(acc_hh[m][n][3]) * cx1
                     + __int2float_rn(acc_x[m][n][3])  * cx2;
            *(float2*)(xgt + (size_t)b * 4096 + col)       = make_float2(f0, f1);
            *(float2*)(xgt + (size_t)(b + 8) * 4096 + col) = make_float2(f2, f3);
        }
}

// ---------------------------------------------------------------------------
// One cell-slice (1/4 of the cell update) on all 256 threads.
// For layer0 (NS=4) xgt supplies the precomputed x contribution.
// ---------------------------------------------------------------------------
template <int NS>
__device__ __forceinline__ void cell_slice(
    int it, float* __restrict__ cst, unsigned char* __restrict__ htile,
    float* __restrict__ hf, const float* __restrict__ part,
    const float* __restrict__ xgt,
    const float* __restrict__ b_ih, const float* __restrict__ b_hh)
{
    int gid  = blockIdx.x * NTHR + threadIdx.x + it * NCTA * NTHR;  // b*1024+n
    int n    = gid & 1023;
    int b    = gid >> 10;
    int tile = n >> 5, nl = n & 31;

    float g4[4];
    #pragma unroll
    for (int g = 0; g < 4; ++g) {
        float sum = b_ih[g * 1024 + n] + b_hh[g * 1024 + n];
        if (xgt) sum += xgt[(size_t)b * 4096 + g * 1024 + n];
        #pragma unroll
        for (int s2 = 0; s2 < NS; ++s2)
            sum += part[((size_t)(s2 * 32 + tile) << 14)
                        + (size_t)b * 128 + g * 32 + nl];
        g4[g] = sum;
    }
    float si = 1.f / (1.f + expf(-g4[0]));
    float sf = 1.f / (1.f + expf(-g4[1]));
    float so = 1.f / (1.f + expf(-g4[3]));
    float cn = sf * cst[gid] + si * tanhf(g4[2]);
    cst[gid] = cn;
    float hv = so * tanhf(cn);
    int hi, lo; q_split(__float2int_rn(hv * 32256.0f), hi, lo);
    unsigned char* tb = htile + (size_t)tile * TILEA;
    tb[off8(b, nl, 0)] = (unsigned char)hi;
    tb[off8(b, nl, 1)] = (unsigned char)lo;
    if (hf) hf[gid] = hv;
}

// ---------------------------------------------------------------------------
// GEMM phase. Per k32 unit: 2 bulk copies (A 8KB, W 8KB), mbarrier pipeline,
// 3 int8 MMAs per (m,n) into 2 exact s32 accumulator sets (hh and cross).
// Warp grid 2(M) x 4(N); warp tile 64x32; 48 MMAs + 12 LDSM per unit.
// ---------------------------------------------------------------------------
template <int CELLK>
__device__ void gemm_phase(
    const unsigned char* __restrict__ pha, int ubase,
    const unsigned char* __restrict__ pw,
    int ulo, int nU, float* __restrict__ pslot,
    unsigned sb, unsigned* ph, bool docell,
    const float* xgt, const float* b_ih, const float* b_hh)
{
    const int tid  = threadIdx.x;
    const int lane = tid & 31;
    const int wid  = tid >> 5;
    const int wm   = wid >> 2;
    const int wn   = wid & 3;

    int acc_hh[4][4][4], acc_x[4][4][4];
    #pragma unroll
    for (int m = 0; m < 4; ++m)
        #pragma unroll
        for (int n = 0; n < 4; ++n)
            #pragma unroll
            for (int r = 0; r < 4; ++r) { acc_hh[m][n][r] = 0; acc_x[m][n][r] = 0; }

    auto issue = [&](int idx) {
        int u = ulo + idx;
        const unsigned char* asrc = pha + (size_t)(u - ubase) * TILEA;
        const unsigned char* wsrc = pw + (size_t)u * TILEW;
        int buf = idx & (NBUF - 1);
        unsigned mbar = sb + (unsigned)buf * 8u;
        unsigned dst  = sb + 1024u + (unsigned)buf * STAGEB;
        mbar_expect_tx(mbar, STAGEB);
        bulk_g2s(dst,         asrc, TILEA, mbar);
        bulk_g2s(dst + TILEA, wsrc, TILEW, mbar);
    };

    if (tid == 0) {
        int np = nU < NBUF ? nU : NBUF;
        for (int p = 0; p < np; ++p) issue(p);
    }

    for (int i = 0; i < nU; ++i) {
        int buf = i & (NBUF - 1);
        mbar_wait(sb + (unsigned)buf * 8u, ph[buf]);
        ph[buf] ^= 1u;
        unsigned bA = sb + 1024u + (unsigned)buf * STAGEB;
        unsigned bW = bA + TILEA;

        unsigned AH[4][4], AL[4][4];
        #pragma unroll
        for (int m = 0; m < 4; ++m) {
            int row = wm * 64 + m * 16 + (lane & 15);
            unsigned rb = bA + (unsigned)(row * 64);
            unsigned sw = (unsigned)((row >> 1) & 3);
            ldsm4(AH[m][0], AH[m][1], AH[m][2], AH[m][3],
                  rb + (((unsigned)(lane >> 4) ^ sw) << 4));
            ldsm4(AL[m][0], AL[m][1], AL[m][2], AL[m][3],
                  rb + (((unsigned)(2 + (lane >> 4)) ^ sw) << 4));
        }
        unsigned WH[4][2], WL[4][2];
        #pragma unroll
        for (int np = 0; np < 2; ++np) {
            int nn = np * 2 + (lane >> 4);
            int rW = wn * 32 + nn * 8 + (lane & 7);
            unsigned rb = bW + (unsigned)(rW * 64);
            unsigned sw = (unsigned)((rW >> 1) & 3);
            unsigned half = (unsigned)((lane >> 3) & 1);
            ldsm4(WH[np*2][0], WH[np*2][1], WH[np*2+1][0], WH[np*2+1][1],
                  rb + ((half ^ sw) << 4));
            ldsm4(WL[np*2][0], WL[np*2][1], WL[np*2+1][0], WL[np*2+1][1],
                  rb + (((2u + half) ^ sw) << 4));
        }

        __syncthreads();     // all threads done reading this buffer
        if (tid == 0 && i + NBUF < nU) issue(i + NBUF);

        // 3 terms, term-outer (consecutive MMAs hit different accumulators)
        #pragma unroll
        for (int m = 0; m < 4; ++m)
            #pragma unroll
            for (int n = 0; n < 4; ++n)
                mma_s8(acc_hh[m][n], AH[m], WH[n]);
        #pragma unroll
        for (int m = 0; m < 4; ++m)
            #pragma unroll
            for (int n = 0; n < 4; ++n)
                mma_s8(acc_x[m][n], AH[m], WL[n]);
        #pragma unroll
        for (int m = 0; m < 4; ++m)
            #pragma unroll
            for (int n = 0; n < 4; ++n)
                mma_s8(acc_x[m][n], AL[m], WH[n]);

        if (CELLK == 2 && docell && (i & 1) == 0 && i < 8)
            cell_slice<8>(i >> 1, g_c1, g_h1t, g_h1f, g_part1, nullptr, b_ih, b_hh);
        else if (CELLK == 1 && docell && (i & 1) == 0 && i < 8)
            cell_slice<4>(i >> 1, g_c0, g_h0t, nullptr, g_part0, xgt, b_ih, b_hh);
    }

    // Epilogue: combine exact int accumulators -> fp32 partials
    const float c1 = (float)(65536.0 / (32256.0 * 1032192.0));
    const float c2 = (float)(256.0   / (32256.0 * 1032192.0));
    #pragma unroll
    for (int m = 0; m < 4; ++m)
        #pragma unroll
        for (int n = 0; n < 4; ++n) {
            int b = wm * 64 + m * 16 + (lane >> 2);
            int c = wn * 32 + n * 8 + (lane & 3) * 2;
            float f0 = __int2float_rn(acc_hh[m][n][0]) * c1
                     + __int2float_rn(acc_x[m][n][0])  * c2;
            float f1 = __int2float_rn(acc_hh[m][n][1]) * c1
                     + __int2float_rn(acc_x[m][n][1])  * c2;
            float f2 = __int2float_rn(acc_hh[m][n][2]) * c1
                     + __int2float_rn(acc_x[m][n][2])  * c2;
            float f3 = __int2float_rn(acc_hh[m][n][3]) * c1
                     + __int2float_rn(acc_x[m][n][3])  * c2;
            *(float2*)(pslot + (size_t)b * 128 + c)       = make_float2(f0, f1);
            *(float2*)(pslot + (size_t)(b + 8) * 128 + c) = make_float2(f2, f3);
        }
}

// ---------------------------------------------------------------------------
// Main persistent kernel: 3 pure-h phases per step (x handled by xgemm).
// ---------------------------------------------------------------------------
__global__ __launch_bounds__(NTHR, 1) void lstm_mma_kernel(
    const float* __restrict__ b_ih0, const float* __restrict__ b_hh0,
    const float* __restrict__ b_ih1, const float* __restrict__ b_hh1,
    const float* __restrict__ Wd,    const float* __restrict__ bd,
    float* __restrict__ out)
{
    extern __shared__ __align__(1024) unsigned char dsmem[];
    const unsigned sb = smem_u32(dsmem);
    const int tid  = threadIdx.x;
    const int cta  = blockIdx.x;
    const int tile = cta & 31;
    const int s    = cta >> 5;

    if (tid == 0) {
        #pragma unroll
        for (int i = 0; i < NBUF; ++i) mbar_init(sb + i * 8u, 1u);
        fence_async();
    }
    __syncthreads();

    unsigned ph[NBUF] = {0, 0, 0, 0, 0, 0, 0, 0};

    const unsigned char* w0 = g_W0t + (size_t)tile * 32u * TILEW;
    const unsigned char* w1 = g_W1t + (size_t)tile * 64u * TILEW;
    float* p0slot  = g_part0 + ((size_t)(s * 32 + tile) << 14);
    float* p1aslot = g_part1 + ((size_t)(s * 32 + tile) << 14);
    float* p1bslot = g_part1 + ((size_t)((4 + s) * 32 + tile) << 14);

    for (int t = 0; t < TQ; ++t) {
        const float* xgt = g_xg + (size_t)t * (BQ * 4096);

        // P1: gemm0(t) = h0 @ W_hh0 [units 8s..8s+8] + interleaved cell1(t-1)
        gemm_phase<2>(g_h0t, 0, w0, s * 8, 8, p0slot, sb, ph,
                      t > 0, nullptr, b_ih1, b_hh1);
        grid_bar();

        // P2: gemm1 h1-half [units 32+8s..+8, A = h1] + interleaved cell0(t)
        gemm_phase<1>(g_h1t, 32, w1, 32 + s * 8, 8, p1aslot, sb, ph,
                      true, xgt, b_ih0, b_hh0);
        grid_bar();

        // P3: gemm1 h0-half [units 8s..+8, A = h0], no cell
        gemm_phase<0>(g_h0t, 0, w1, s * 8, 8, p1bslot, sb, ph,
                      false, nullptr, nullptr, nullptr);
        grid_bar();
    }

    // Final cell1(255) on all threads
    #pragma unroll
    for (int it = 0; it < 4; ++it)
        cell_slice<8>(it, g_c1, g_h1t, g_h1f, g_part1, nullptr, b_ih1, b_hh1);
    grid_bar();

    // Dense head: CTA b computes out[b][0..1] from fp32 h1
    {
        float* red = (float*)dsmem;
        const int b = cta;
        float s0 = 0.f, s1 = 0.f;
        for (int n = tid; n < HQ; n += NTHR) {
            float hv = g_h1f[(size_t)b * HQ + n];
            s0 += hv * Wd[n];
            s1 += hv * Wd[HQ + n];
        }
        __syncthreads();
        red[tid] = s0; red[NTHR + tid] = s1;
        __syncthreads();
        for (int off = NTHR / 2; off > 0; off >>= 1) {
            if (tid < off) {
                red[tid] += red[tid + off];
                red[NTHR + tid] += red[NTHR + tid + off];
            }
            __syncthreads();
        }
        if (tid == 0) {
            out[b * 2 + 0] = tanhf(red[0] + bd[0]);
            out[b * 2 + 1] = tanhf(red[NTHR] + bd[1]);
        }
    }
}

// ---------------------------------------------------------------------------
// Launch: 5 graph nodes
// ---------------------------------------------------------------------------
extern "C" void kernel_launch(void* const* d_in, const int* in_sizes, int n_in,
                              void* d_out, int out_size)
{
    const float* x     = (const float*)d_in[0];
    const float* W_ih0 = (const float*)d_in[1];
    const float* W_hh0 = (const float*)d_in[2];
    const float* b_ih0 = (const float*)d_in[3];
    const float* b_hh0 = (const float*)d_in[4];
    const float* W_ih1 = (const float*)d_in[5];
    const float* W_hh1 = (const float*)d_in[6];
    const float* b_ih1 = (const float*)d_in[7];
    const float* b_hh1 = (const float*)d_in[8];
    const float* Wd    = (const float*)d_in[9];
    const float* bd    = (const float*)d_in[10];
    float* out = (float*)d_out;

    const int smem_main  = 1024 + NBUF * (int)STAGEB;   // 132096
    const int smem_xgemm = 1024 + 4 * (int)STAGEB;      // 66560
    cudaFuncSetAttribute(lstm_mma_kernel,
                         cudaFuncAttributeMaxDynamicSharedMemorySize, smem_main);
    cudaFuncSetAttribute(xgemm_kernel,
                         cudaFuncAttributeMaxDynamicSharedMemorySize, smem_xgemm);

    init_state_kernel<<<(BQ * HQ + 255) / 256, 256>>>();
    init_x_kernel<<<(BQ * TQ * INQ + 255) / 256, 256>>>(x);
    init_w_kernel<<<2048, 256>>>(W_ih0, W_hh0, W_ih1, W_hh1);
    xgemm_kernel<<<dim3(32, 256), 256, smem_xgemm>>>();

    lstm_mma_kernel<<<NCTA, NTHR, smem_main>>>(
        b_ih0, b_hh0, b_ih1, b_hh1, Wd, bd, out);
}

// round 13
// speedup vs baseline: 2.6980x; 2.6980x over previous
#include <cuda_runtime.h>
#include <cuda_bf16.h>
#include <math.h>

// Problem constants
#define BQ   128
#define TQ   256
#define INQ  128
#define HQ   1024
#define NCTA 128      // 32 col-tiles x 4 unit-splits; all co-resident
#define NTHR 256

#define NU0  36       // layer0 units of k32: 4 (x) + 32 (h0)
#define TILE16K 16384u
#define STAGEB  32768u
#define NBUF 4

// ---------------------------------------------------------------------------
// Device globals. Operand tiles contiguous + pre-swizzled (one cp.async.bulk
// per operand per k32 unit). Tile (16KB) = [hi 8KB | lo 8KB]; within 8KB:
// byte off = r*64 + ((seg ^ ((r>>1)&3))<<4) + (k&7)*2,  seg = k>>3.
// ---------------------------------------------------------------------------
__device__ __align__(1024) unsigned char g_W0t[32u * NU0 * TILE16K];
__device__ __align__(1024) unsigned char g_W1t[32u * 64u * TILE16K];
__device__ __align__(1024) unsigned char g_xt[(unsigned)TQ * 4u * TILE16K];
__device__ __align__(1024) unsigned char g_h0t[32u * TILE16K];
__device__ __align__(1024) unsigned char g_h1t[32u * TILE16K];
__device__ float g_h1f[BQ * HQ];
__device__ float g_c0[BQ * HQ];
__device__ float g_c1[BQ * HQ];
// Partial gate sums: layer0 2 slots, layer1 3 slots: [slot*32+tile][b][c]
__device__ float g_part0[2u * 32u * 128u * 128u];
__device__ float g_part1[3u * 32u * 128u * 128u];

__device__ unsigned g_bar_count = 0;
__device__ unsigned g_bar_gen   = 0;

__device__ __forceinline__ unsigned off_in_tile(int r, int k) {
    return (unsigned)(r * 64 + ((((k >> 3) ^ ((r >> 1) & 3))) << 4) + ((k & 7) << 1));
}

// ---------------------------------------------------------------------------
// PTX helpers (sm_80/90 baseline — no 'a'-gated features)
// ---------------------------------------------------------------------------
__device__ __forceinline__ unsigned smem_u32(const void* p) {
    unsigned a;
    asm("{ .reg .u64 t; cvta.to.shared.u64 t, %1; cvt.u32.u64 %0, t; }"
        : "=r"(a) : "l"(p));
    return a;
}
__device__ __forceinline__ void mbar_init(unsigned mbar, unsigned cnt) {
    asm volatile("mbarrier.init.shared.b64 [%0], %1;" :: "r"(mbar), "r"(cnt) : "memory");
}
__device__ __forceinline__ void mbar_wait(unsigned mbar, unsigned parity) {
    asm volatile(
        "{\n\t.reg .pred P;\n\t"
        "W_%=:\n\t"
        "mbarrier.try_wait.parity.acquire.cta.shared::cta.b64 P, [%0], %1, 0x989680;\n\t"
        "@!P bra W_%=;\n\t}"
        :: "r"(mbar), "r"(parity) : "memory");
}
__device__ __forceinline__ void mbar_expect_tx(unsigned mbar, unsigned bytes) {
    asm volatile("mbarrier.arrive.expect_tx.shared.b64 _, [%0], %1;"
                 :: "r"(mbar), "r"(bytes) : "memory");
}
__device__ __forceinline__ void bulk_g2s(unsigned dst, const void* src,
                                         unsigned bytes, unsigned mbar) {
    asm volatile(
        "cp.async.bulk.shared::cluster.global.mbarrier::complete_tx::bytes "
        "[%0], [%1], %2, [%3];"
        :: "r"(dst), "l"(src), "r"(bytes), "r"(mbar) : "memory");
}
__device__ __forceinline__ void fence_async() {
    asm volatile("fence.proxy.async.shared::cta;" ::: "memory");
}
__device__ __forceinline__ void ldsm4(unsigned& r0, unsigned& r1,
                                      unsigned& r2, unsigned& r3, unsigned a) {
    asm volatile("ldmatrix.sync.aligned.m8n8.x4.shared.b16 {%0,%1,%2,%3}, [%4];"
                 : "=r"(r0), "=r"(r1), "=r"(r2), "=r"(r3) : "r"(a));
}
__device__ __forceinline__ void mma16816(float* d, const unsigned* a, const unsigned* b) {
    asm volatile(
        "mma.sync.aligned.m16n8k16.row.col.f32.bf16.bf16.f32 "
        "{%0,%1,%2,%3}, {%4,%5,%6,%7}, {%8,%9}, {%0,%1,%2,%3};"
        : "+f"(d[0]), "+f"(d[1]), "+f"(d[2]), "+f"(d[3])
        : "r"(a[0]), "r"(a[1]), "r"(a[2]), "r"(a[3]), "r"(b[0]), "r"(b[1]));
}

// ---------------------------------------------------------------------------
// Grid barrier (all NCTA CTAs co-resident)
// ---------------------------------------------------------------------------
__device__ __forceinline__ void grid_bar() {
    __syncthreads();
    if (threadIdx.x == 0) {
        __threadfence();
        unsigned my = *(volatile unsigned*)&g_bar_gen;
        if (atomicAdd(&g_bar_count, 1u) == NCTA - 1u) {
            *(volatile unsigned*)&g_bar_count = 0;
            __threadfence();
            atomicExch(&g_bar_gen, my + 1u);
        } else {
            while (*(volatile unsigned*)&g_bar_gen == my) { }
        }
        __threadfence();
    }
    __syncthreads();
}

// ---------------------------------------------------------------------------
// Init kernels (per replay; deterministic)
// ---------------------------------------------------------------------------
__device__ __forceinline__ void split_store(float v, unsigned char* hi_ptr) {
    __nv_bfloat16 h = __float2bfloat16(v);
    __nv_bfloat16 l = __float2bfloat16(v - __bfloat162float(h));
    *(__nv_bfloat16*)hi_ptr = h;
    *(__nv_bfloat16*)(hi_ptr + 8192) = l;
}

__global__ void init_state_kernel() {
    int i = blockIdx.x * blockDim.x + threadIdx.x;
    if (i < (32 * 16384) / 4) {
        ((unsigned*)g_h0t)[i] = 0u;
        ((unsigned*)g_h1t)[i] = 0u;
    }
    if (i < BQ * HQ) { g_c0[i] = 0.f; g_c1[i] = 0.f; }
}
__global__ void init_x_kernel(const float* __restrict__ x) {
    int i = blockIdx.x * blockDim.x + threadIdx.x;   // = b*32768 + t*128 + k
    if (i >= BQ * TQ * INQ) return;
    int k = i & 127, t = (i >> 7) & 255, b = i >> 15;
    int u = k >> 5, kl = k & 31;
    unsigned char* dst = g_xt + (size_t)(t * 4 + u) * TILE16K + off_in_tile(b, kl);
    split_store(x[i], dst);
}
__global__ void init_w_kernel(
    const float* __restrict__ W_ih0, const float* __restrict__ W_hh0,
    const float* __restrict__ W_ih1, const float* __restrict__ W_hh1)
{
    const unsigned N0 = 32u * NU0 * 4096u;
    const unsigned N1 = 32u * 64u * 4096u;
    for (unsigned i = blockIdx.x * blockDim.x + threadIdx.x; i < N0 + N1;
         i += gridDim.x * blockDim.x) {
        if (i < N0) {
            unsigned kl = i & 31u, r = (i >> 5) & 127u;
            unsigned rest = i >> 12, u = rest % NU0, tile = rest / NU0;
            unsigned gcol = ((r >> 5) << 10) + tile * 32u + (r & 31u);
            unsigned k = u * 32u + kl;
            float v = (k < 128u) ? W_ih0[(size_t)gcol * 128u + k]
                                 : W_hh0[(size_t)gcol * 1024u + (k - 128u)];
            split_store(v, g_W0t + (size_t)(tile * NU0 + u) * TILE16K + off_in_tile(r, kl));
        } else {
            unsigned j = i - N0;
            unsigned kl = j & 31u, r = (j >> 5) & 127u;
            unsigned rest = j >> 12, u = rest & 63u, tile = rest >> 6;
            unsigned gcol = ((r >> 5) << 10) + tile * 32u + (r & 31u);
            unsigned k = u * 32u + kl;
            float v = (k < 1024u) ? W_ih1[(size_t)gcol * 1024u + k]
                                  : W_hh1[(size_t)gcol * 1024u + (k - 1024u)];
            split_store(v, g_W1t + (size_t)(tile * 64u + u) * TILE16K + off_in_tile(r, kl));
        }
    }
}

// ---------------------------------------------------------------------------
// One cell-slice (1/4 of one cell's update) on all 256 threads of all CTAs.
// NS = number of partial slots to sum.
// ---------------------------------------------------------------------------
template <int NS>
__device__ __forceinline__ void cell_slice(
    int it, float* __restrict__ cst, unsigned char* __restrict__ htile,
    float* __restrict__ hf, const float* __restrict__ part,
    const float* __restrict__ b_ih, const float* __restrict__ b_hh)
{
    int gid  = blockIdx.x * NTHR + threadIdx.x + it * NCTA * NTHR;  // b*1024+n
    int n    = gid & 1023;
    int b    = gid >> 10;
    int tile = n >> 5, nl = n & 31;

    float g4[4];
    #pragma unroll
    for (int g = 0; g < 4; ++g) {
        float sum = b_ih[g * 1024 + n] + b_hh[g * 1024 + n];
        #pragma unroll
        for (int s2 = 0; s2 < NS; ++s2)
            sum += part[((size_t)(s2 * 32 + tile) << 14)
                        + (size_t)b * 128 + g * 32 + nl];
        g4[g] = sum;
    }
    float si = 1.f / (1.f + expf(-g4[0]));
    float sf = 1.f / (1.f + expf(-g4[1]));
    float so = 1.f / (1.f + expf(-g4[3]));
    float cn = sf * cst[gid] + si * tanhf(g4[2]);
    cst[gid] = cn;
    float hv = so * tanhf(cn);
    split_store(hv, htile + (size_t)tile * TILE16K + off_in_tile(b, nl));
    if (hf) hf[gid] = hv;
}

// ---------------------------------------------------------------------------
// GEMM segment. Per k32 unit: 2 bulk copies (A 16KB, W 16KB), mbarrier
// pipeline, 3-term split bf16 HMMA (term-outer). Warp grid 2(M) x 4(N).
// Buffers + phase state (ph) persist across calls.
// ---------------------------------------------------------------------------
__device__ void gemm_seg(
    const unsigned char* __restrict__ pxa, int uxsplit,
    const unsigned char* __restrict__ pha,
    const unsigned char* __restrict__ pw,
    int ulo, int nU, float* __restrict__ pslot,
    unsigned sb, unsigned* ph)
{
    const int tid  = threadIdx.x;
    const int lane = tid & 31;
    const int wid  = tid >> 5;
    const int wm   = wid >> 2;
    const int wn   = wid & 3;

    float acc[4][4][4];
    #pragma unroll
    for (int m = 0; m < 4; ++m)
        #pragma unroll
        for (int n = 0; n < 4; ++n)
            #pragma unroll
            for (int r = 0; r < 4; ++r) acc[m][n][r] = 0.f;

    auto issue = [&](int idx) {
        int u = ulo + idx;
        const unsigned char* asrc = (u < uxsplit)
            ? pxa + (size_t)u * TILE16K
            : pha + (size_t)(u - uxsplit) * TILE16K;
        const unsigned char* wsrc = pw + (size_t)u * TILE16K;
        int buf = idx & (NBUF - 1);
        unsigned mbar = sb + (unsigned)buf * 8u;
        unsigned dst  = sb + 1024u + (unsigned)buf * STAGEB;
        mbar_expect_tx(mbar, STAGEB);
        bulk_g2s(dst,            asrc, TILE16K, mbar);
        bulk_g2s(dst + TILE16K,  wsrc, TILE16K, mbar);
    };

    if (tid == 0) {
        int np = nU < NBUF ? nU : NBUF;
        for (int p = 0; p < np; ++p) issue(p);
    }

    for (int i = 0; i < nU; ++i) {
        int buf = i & (NBUF - 1);
        mbar_wait(sb + (unsigned)buf * 8u, ph[buf]);
        ph[buf] ^= 1u;
        unsigned bA = sb + 1024u + (unsigned)buf * STAGEB;   // A hi (lo +8192)
        unsigned bW = bA + TILE16K;                          // W hi (lo +8192)

        #pragma unroll
        for (int j = 0; j < 2; ++j) {
            int rA = wm * 64 + (lane & 15);
            unsigned aH = bA + (unsigned)(rA * 64)
                        + ((unsigned)((j * 2 + (lane >> 4)) ^ ((rA >> 1) & 3)) << 4);
            unsigned AH[4][4], AL[4][4];
            #pragma unroll
            for (int m = 0; m < 4; ++m) {
                ldsm4(AH[m][0], AH[m][1], AH[m][2], AH[m][3], aH + m * 1024u);
                ldsm4(AL[m][0], AL[m][1], AL[m][2], AL[m][3], aH + m * 1024u + 8192u);
            }
            unsigned WH[4][2], WL[4][2];
            #pragma unroll
            for (int np = 0; np < 2; ++np) {
                int nn = np * 2 + (lane >> 4);
                int rW = wn * 32 + nn * 8 + (lane & 7);
                unsigned wAddr = bW + (unsigned)(rW * 64)
                    + ((unsigned)((j * 2 + ((lane >> 3) & 1)) ^ ((rW >> 1) & 3)) << 4);
                ldsm4(WH[np*2][0], WH[np*2][1], WH[np*2+1][0], WH[np*2+1][1], wAddr);
                ldsm4(WL[np*2][0], WL[np*2][1], WL[np*2+1][0], WL[np*2+1][1],
                      wAddr + 8192u);
            }
            if (j == 1) {
                __syncthreads();     // all threads done reading this buffer
                if (tid == 0 && i + NBUF < nU) issue(i + NBUF);
            }
            #pragma unroll
            for (int m = 0; m < 4; ++m)
                #pragma unroll
                for (int n = 0; n < 4; ++n)
                    mma16816(acc[m][n], AH[m], WH[n]);
            #pragma unroll
            for (int m = 0; m < 4; ++m)
                #pragma unroll
                for (int n = 0; n < 4; ++n)
                    mma16816(acc[m][n], AL[m], WH[n]);
            #pragma unroll
            for (int m = 0; m < 4; ++m)
                #pragma unroll
                for (int n = 0; n < 4; ++n)
                    mma16816(acc[m][n], AH[m], WL[n]);
        }
    }

    // Epilogue: D fragments -> pslot[b][c]
    #pragma unroll
    for (int m = 0; m < 4; ++m)
        #pragma unroll
        for (int n = 0; n < 4; ++n) {
            int b = wm * 64 + m * 16 + (lane >> 2);
            int c = wn * 32 + n * 8 + (lane & 3) * 2;
            *(float2*)(pslot + (size_t)b * 128 + c) =
                make_float2(acc[m][n][0], acc[m][n][1]);
            *(float2*)(pslot + (size_t)(b + 8) * 128 + c) =
                make_float2(acc[m][n][2], acc[m][n][3]);
        }
}

// ---------------------------------------------------------------------------
// Main persistent kernel: per step ONE merged gemm phase (gemm0(t) and
// gemm1(t-1) are independent) + ONE cell phase. 2 grid bars per step.
//   s0: L0 units [0,25)                    -> part0 slot0
//   s1: L0 units [25,36) -> part0 slot1;  L1 units [0,14)  -> part1 slot0
//   s2: L1 units [14,39)                   -> part1 slot1
//   s3: L1 units [39,64)                   -> part1 slot2
// ---------------------------------------------------------------------------
__global__ __launch_bounds__(NTHR, 1) void lstm_mma_kernel(
    const float* __restrict__ b_ih0, const float* __restrict__ b_hh0,
    const float* __restrict__ b_ih1, const float* __restrict__ b_hh1,
    const float* __restrict__ Wd,    const float* __restrict__ bd,
    float* __restrict__ out)
{
    extern __shared__ __align__(1024) unsigned char dsmem[];
    const unsigned sb = smem_u32(dsmem);
    const int tid  = threadIdx.x;
    const int cta  = blockIdx.x;
    const int tile = cta & 31;
    const int s    = cta >> 5;

    if (tid == 0) {
        #pragma unroll
        for (int i = 0; i < NBUF; ++i) mbar_init(sb + i * 8u, 1u);
        fence_async();
    }
    __syncthreads();

    unsigned ph[NBUF] = {0, 0, 0, 0};

    const unsigned char* w0 = g_W0t + (size_t)tile * NU0 * TILE16K;
    const unsigned char* w1 = g_W1t + (size_t)tile * 64u * TILE16K;
    float* p0s0 = g_part0 + ((size_t)(0 * 32 + tile) << 14);
    float* p0s1 = g_part0 + ((size_t)(1 * 32 + tile) << 14);
    float* p1s0 = g_part1 + ((size_t)(0 * 32 + tile) << 14);
    float* p1s1 = g_part1 + ((size_t)(1 * 32 + tile) << 14);
    float* p1s2 = g_part1 + ((size_t)(2 * 32 + tile) << 14);

    for (int t = 0; t <= TQ; ++t) {
        // ---- G phase: gemm0(t) [if t<TQ] and gemm1(t-1) [if t>0]
        const unsigned char* xt = g_xt + (size_t)t * 4 * TILE16K;
        if (s == 0) {
            if (t < TQ)
                gemm_seg(xt, 4, g_h0t, w0, 0, 25, p0s0, sb, ph);
        } else if (s == 1) {
            if (t < TQ)
                gemm_seg(xt, 4, g_h0t, w0, 25, 11, p0s1, sb, ph);
            if (t > 0)
                gemm_seg(g_h0t, 32, g_h1t, w1, 0, 14, p1s0, sb, ph);
        } else if (s == 2) {
            if (t > 0)
                gemm_seg(g_h0t, 32, g_h1t, w1, 14, 25, p1s1, sb, ph);
        } else {
            if (t > 0)
                gemm_seg(g_h0t, 32, g_h1t, w1, 39, 25, p1s2, sb, ph);
        }
        grid_bar();

        // ---- C phase: cell0(t) [if t<TQ] and cell1(t-1) [if t>0]
        if (t < TQ) {
            #pragma unroll
            for (int it = 0; it < 4; ++it)
                cell_slice<2>(it, g_c0, g_h0t, nullptr, g_part0, b_ih0, b_hh0);
        }
        if (t > 0) {
            float* hf = (t == TQ) ? g_h1f : nullptr;
            #pragma unroll
            for (int it = 0; it < 4; ++it)
                cell_slice<3>(it, g_c1, g_h1t, hf, g_part1, b_ih1, b_hh1);
        }
        grid_bar();
    }

    // Dense head: CTA b computes out[b][0..1] from fp32 h1
    {
        float* red = (float*)dsmem;
        const int b = cta;
        float s0 = 0.f, s1 = 0.f;
        for (int n = tid; n < HQ; n += NTHR) {
            float hv = g_h1f[(size_t)b * HQ + n];
            s0 += hv * Wd[n];
            s1 += hv * Wd[HQ + n];
        }
        __syncthreads();
        red[tid] = s0; red[NTHR + tid] = s1;
        __syncthreads();
        for (int off = NTHR / 2; off > 0; off >>= 1) {
            if (tid < off) {
                red[tid] += red[tid + off];
                red[NTHR + tid] += red[NTHR + tid + off];
            }
            __syncthreads();
        }
        if (tid == 0) {
            out[b * 2 + 0] = tanhf(red[0] + bd[0]);
            out[b * 2 + 1] = tanhf(red[NTHR] + bd[1]);
        }
    }
}

// ---------------------------------------------------------------------------
// Launch: 4 graph nodes
// ---------------------------------------------------------------------------
extern "C" void kernel_launch(void* const* d_in, const int* in_sizes, int n_in,
                              void* d_out, int out_size)
{
    const float* x     = (const float*)d_in[0];
    const float* W_ih0 = (const float*)d_in[1];
    const float* W_hh0 = (const float*)d_in[2];
    const float* b_ih0 = (const float*)d_in[3];
    const float* b_hh0 = (const float*)d_in[4];
    const float* W_ih1 = (const float*)d_in[5];
    const float* W_hh1 = (const float*)d_in[6];
    const float* b_ih1 = (const float*)d_in[7];
    const float* b_hh1 = (const float*)d_in[8];
    const float* Wd    = (const float*)d_in[9];
    const float* bd    = (const float*)d_in[10];
    float* out = (float*)d_out;

    const int smem_bytes = 1024 + NBUF * (int)STAGEB;   // 132096
    cudaFuncSetAttribute(lstm_mma_kernel,
                         cudaFuncAttributeMaxDynamicSharedMemorySize, smem_bytes);

    init_state_kernel<<<(32 * 16384 / 4 + 255) / 256, 256>>>();
    init_x_kernel<<<(BQ * TQ * INQ + 255) / 256, 256>>>(x);
    init_w_kernel<<<2048, 256>>>(W_ih0, W_hh0, W_ih1, W_hh1);

    lstm_mma_kernel<<<NCTA, NTHR, smem_bytes>>>(
        b_ih0, b_hh0, b_ih1, b_hh1, Wd, bd, out);
}

// round 14
// speedup vs baseline: 2.8579x; 1.0592x over previous
#include <cuda_runtime.h>
#include <cuda_bf16.h>
#include <math.h>

// Problem constants
#define BQ   128
#define TQ   256
#define INQ  128
#define HQ   1024
#define NCTA 128      // 32 col-tiles x 4 unit-splits; all co-resident
#define NTHR 512      // 16 warps -> 4 per SMSP (latency hiding)

#define NU0  36       // layer0 units of k32: 4 (x) + 32 (h0)
#define TILE16K 16384u
#define STAGEB  32768u
#define NBUF 4

// ---------------------------------------------------------------------------
// Device globals. Operand tiles contiguous + pre-swizzled (one cp.async.bulk
// per operand per k32 unit). Tile (16KB) = [hi 8KB | lo 8KB]; within 8KB:
// byte off = r*64 + ((seg ^ ((r>>1)&3))<<4) + (k&7)*2,  seg = k>>3.
// ---------------------------------------------------------------------------
__device__ __align__(1024) unsigned char g_W0t[32u * NU0 * TILE16K];
__device__ __align__(1024) unsigned char g_W1t[32u * 64u * TILE16K];
__device__ __align__(1024) unsigned char g_xt[(unsigned)TQ * 4u * TILE16K];
__device__ __align__(1024) unsigned char g_h0t[32u * TILE16K];
__device__ __align__(1024) unsigned char g_h1t[32u * TILE16K];
__device__ float g_h1f[BQ * HQ];
__device__ float g_c0[BQ * HQ];
__device__ float g_c1[BQ * HQ];
// Partial gate sums: layer0 2 slots, layer1 3 slots: [slot*32+tile][b][c]
__device__ float g_part0[2u * 32u * 128u * 128u];
__device__ float g_part1[3u * 32u * 128u * 128u];

__device__ unsigned g_bar_count = 0;
__device__ unsigned g_bar_gen   = 0;

__device__ __forceinline__ unsigned off_in_tile(int r, int k) {
    return (unsigned)(r * 64 + ((((k >> 3) ^ ((r >> 1) & 3))) << 4) + ((k & 7) << 1));
}

// ---------------------------------------------------------------------------
// PTX helpers (sm_80/90 baseline — no 'a'-gated features)
// ---------------------------------------------------------------------------
__device__ __forceinline__ unsigned smem_u32(const void* p) {
    unsigned a;
    asm("{ .reg .u64 t; cvta.to.shared.u64 t, %1; cvt.u32.u64 %0, t; }"
        : "=r"(a) : "l"(p));
    return a;
}
__device__ __forceinline__ void mbar_init(unsigned mbar, unsigned cnt) {
    asm volatile("mbarrier.init.shared.b64 [%0], %1;" :: "r"(mbar), "r"(cnt) : "memory");
}
__device__ __forceinline__ void mbar_wait(unsigned mbar, unsigned parity) {
    asm volatile(
        "{\n\t.reg .pred P;\n\t"
        "W_%=:\n\t"
        "mbarrier.try_wait.parity.acquire.cta.shared::cta.b64 P, [%0], %1, 0x989680;\n\t"
        "@!P bra W_%=;\n\t}"
        :: "r"(mbar), "r"(parity) : "memory");
}
__device__ __forceinline__ void mbar_expect_tx(unsigned mbar, unsigned bytes) {
    asm volatile("mbarrier.arrive.expect_tx.shared.b64 _, [%0], %1;"
                 :: "r"(mbar), "r"(bytes) : "memory");
}
__device__ __forceinline__ void bulk_g2s(unsigned dst, const void* src,
                                         unsigned bytes, unsigned mbar) {
    asm volatile(
        "cp.async.bulk.shared::cluster.global.mbarrier::complete_tx::bytes "
        "[%0], [%1], %2, [%3];"
        :: "r"(dst), "l"(src), "r"(bytes), "r"(mbar) : "memory");
}
__device__ __forceinline__ void fence_async() {
    asm volatile("fence.proxy.async.shared::cta;" ::: "memory");
}
__device__ __forceinline__ void ldsm4(unsigned& r0, unsigned& r1,
                                      unsigned& r2, unsigned& r3, unsigned a) {
    asm volatile("ldmatrix.sync.aligned.m8n8.x4.shared.b16 {%0,%1,%2,%3}, [%4];"
                 : "=r"(r0), "=r"(r1), "=r"(r2), "=r"(r3) : "r"(a));
}
__device__ __forceinline__ void mma16816(float* d, const unsigned* a, const unsigned* b) {
    asm volatile(
        "mma.sync.aligned.m16n8k16.row.col.f32.bf16.bf16.f32 "
        "{%0,%1,%2,%3}, {%4,%5,%6,%7}, {%8,%9}, {%0,%1,%2,%3};"
        : "+f"(d[0]), "+f"(d[1]), "+f"(d[2]), "+f"(d[3])
        : "r"(a[0]), "r"(a[1]), "r"(a[2]), "r"(a[3]), "r"(b[0]), "r"(b[1]));
}

// ---------------------------------------------------------------------------
// Grid barrier (all NCTA CTAs co-resident)
// ---------------------------------------------------------------------------
__device__ __forceinline__ void grid_bar() {
    __syncthreads();
    if (threadIdx.x == 0) {
        __threadfence();
        unsigned my = *(volatile unsigned*)&g_bar_gen;
        if (atomicAdd(&g_bar_count, 1u) == NCTA - 1u) {
            *(volatile unsigned*)&g_bar_count = 0;
            __threadfence();
            atomicExch(&g_bar_gen, my + 1u);
        } else {
            while (*(volatile unsigned*)&g_bar_gen == my) { }
        }
        __threadfence();
    }
    __syncthreads();
}

// ---------------------------------------------------------------------------
// Init kernels (per replay; deterministic)
// ---------------------------------------------------------------------------
__device__ __forceinline__ void split_store(float v, unsigned char* hi_ptr) {
    __nv_bfloat16 h = __float2bfloat16(v);
    __nv_bfloat16 l = __float2bfloat16(v - __bfloat162float(h));
    *(__nv_bfloat16*)hi_ptr = h;
    *(__nv_bfloat16*)(hi_ptr + 8192) = l;
}

__global__ void init_state_kernel() {
    int i = blockIdx.x * blockDim.x + threadIdx.x;
    if (i < (32 * 16384) / 4) {
        ((unsigned*)g_h0t)[i] = 0u;
        ((unsigned*)g_h1t)[i] = 0u;
    }
    if (i < BQ * HQ) { g_c0[i] = 0.f; g_c1[i] = 0.f; }
}
__global__ void init_x_kernel(const float* __restrict__ x) {
    int i = blockIdx.x * blockDim.x + threadIdx.x;   // = b*32768 + t*128 + k
    if (i >= BQ * TQ * INQ) return;
    int k = i & 127, t = (i >> 7) & 255, b = i >> 15;
    int u = k >> 5, kl = k & 31;
    unsigned char* dst = g_xt + (size_t)(t * 4 + u) * TILE16K + off_in_tile(b, kl);
    split_store(x[i], dst);
}
__global__ void init_w_kernel(
    const float* __restrict__ W_ih0, const float* __restrict__ W_hh0,
    const float* __restrict__ W_ih1, const float* __restrict__ W_hh1)
{
    const unsigned N0 = 32u * NU0 * 4096u;
    const unsigned N1 = 32u * 64u * 4096u;
    for (unsigned i = blockIdx.x * blockDim.x + threadIdx.x; i < N0 + N1;
         i += gridDim.x * blockDim.x) {
        if (i < N0) {
            unsigned kl = i & 31u, r = (i >> 5) & 127u;
            unsigned rest = i >> 12, u = rest % NU0, tile = rest / NU0;
            unsigned gcol = ((r >> 5) << 10) + tile * 32u + (r & 31u);
            unsigned k = u * 32u + kl;
            float v = (k < 128u) ? W_ih0[(size_t)gcol * 128u + k]
                                 : W_hh0[(size_t)gcol * 1024u + (k - 128u)];
            split_store(v, g_W0t + (size_t)(tile * NU0 + u) * TILE16K + off_in_tile(r, kl));
        } else {
            unsigned j = i - N0;
            unsigned kl = j & 31u, r = (j >> 5) & 127u;
            unsigned rest = j >> 12, u = rest & 63u, tile = rest >> 6;
            unsigned gcol = ((r >> 5) << 10) + tile * 32u + (r & 31u);
            unsigned k = u * 32u + kl;
            float v = (k < 1024u) ? W_ih1[(size_t)gcol * 1024u + k]
                                  : W_hh1[(size_t)gcol * 1024u + (k - 1024u)];
            split_store(v, g_W1t + (size_t)(tile * 64u + u) * TILE16K + off_in_tile(r, kl));
        }
    }
}

// ---------------------------------------------------------------------------
// One cell-slice (1/2 of one cell's update at 512 threads).
// NS = number of partial slots to sum.
// ---------------------------------------------------------------------------
template <int NS>
__device__ __forceinline__ void cell_slice(
    int it, float* __restrict__ cst, unsigned char* __restrict__ htile,
    float* __restrict__ hf, const float* __restrict__ part,
    const float* __restrict__ b_ih, const float* __restrict__ b_hh)
{
    int gid  = blockIdx.x * NTHR + threadIdx.x + it * NCTA * NTHR;  // b*1024+n
    int n    = gid & 1023;
    int b    = gid >> 10;
    int tile = n >> 5, nl = n & 31;

    float g4[4];
    #pragma unroll
    for (int g = 0; g < 4; ++g) {
        float sum = b_ih[g * 1024 + n] + b_hh[g * 1024 + n];
        #pragma unroll
        for (int s2 = 0; s2 < NS; ++s2)
            sum += part[((size_t)(s2 * 32 + tile) << 14)
                        + (size_t)b * 128 + g * 32 + nl];
        g4[g] = sum;
    }
    float si = 1.f / (1.f + expf(-g4[0]));
    float sf = 1.f / (1.f + expf(-g4[1]));
    float so = 1.f / (1.f + expf(-g4[3]));
    float cn = sf * cst[gid] + si * tanhf(g4[2]);
    cst[gid] = cn;
    float hv = so * tanhf(cn);
    split_store(hv, htile + (size_t)tile * TILE16K + off_in_tile(b, nl));
    if (hf) hf[gid] = hv;
}

// ---------------------------------------------------------------------------
// GEMM segment. Per k32 unit: 2 bulk copies (A 16KB, W 16KB), mbarrier
// pipeline, 3-term split bf16 HMMA (term-outer). Warp grid 4(M) x 4(N),
// warp tile 32x32 (acc = 32 regs -> fits 128-reg cap at 512 threads).
// Buffers + phase state (ph) persist across calls.
// ---------------------------------------------------------------------------
__device__ void gemm_seg(
    const unsigned char* __restrict__ pxa, int uxsplit,
    const unsigned char* __restrict__ pha,
    const unsigned char* __restrict__ pw,
    int ulo, int nU, float* __restrict__ pslot,
    unsigned sb, unsigned* ph)
{
    const int tid  = threadIdx.x;
    const int lane = tid & 31;
    const int wid  = tid >> 5;
    const int wm   = wid >> 2;   // 0..3
    const int wn   = wid & 3;    // 0..3

    float acc[2][4][4];
    #pragma unroll
    for (int m = 0; m < 2; ++m)
        #pragma unroll
        for (int n = 0; n < 4; ++n)
            #pragma unroll
            for (int r = 0; r < 4; ++r) acc[m][n][r] = 0.f;

    auto issue = [&](int idx) {
        int u = ulo + idx;
        const unsigned char* asrc = (u < uxsplit)
            ? pxa + (size_t)u * TILE16K
            : pha + (size_t)(u - uxsplit) * TILE16K;
        const unsigned char* wsrc = pw + (size_t)u * TILE16K;
        int buf = idx & (NBUF - 1);
        unsigned mbar = sb + (unsigned)buf * 8u;
        unsigned dst  = sb + 1024u + (unsigned)buf * STAGEB;
        mbar_expect_tx(mbar, STAGEB);
        bulk_g2s(dst,            asrc, TILE16K, mbar);
        bulk_g2s(dst + TILE16K,  wsrc, TILE16K, mbar);
    };

    if (tid == 0) {
        int np = nU < NBUF ? nU : NBUF;
        for (int p = 0; p < np; ++p) issue(p);
    }

    for (int i = 0; i < nU; ++i) {
        int buf = i & (NBUF - 1);
        mbar_wait(sb + (unsigned)buf * 8u, ph[buf]);
        ph[buf] ^= 1u;
        unsigned bA = sb + 1024u + (unsigned)buf * STAGEB;   // A hi (lo +8192)
        unsigned bW = bA + TILE16K;                          // W hi (lo +8192)

        #pragma unroll
        for (int j = 0; j < 2; ++j) {
            // A fragments: 2 m-tiles (32 rows) x (hi,lo)
            int rA = wm * 32 + (lane & 15);
            unsigned aH = bA + (unsigned)(rA * 64)
                        + ((unsigned)((j * 2 + (lane >> 4)) ^ ((rA >> 1) & 3)) << 4);
            unsigned AH[2][4], AL[2][4];
            #pragma unroll
            for (int m = 0; m < 2; ++m) {
                ldsm4(AH[m][0], AH[m][1], AH[m][2], AH[m][3], aH + m * 1024u);
                ldsm4(AL[m][0], AL[m][1], AL[m][2], AL[m][3], aH + m * 1024u + 8192u);
            }
            // W fragments: 4 n8-tiles; 2 ldsm4 per (hi,lo)
            unsigned WH[4][2], WL[4][2];
            #pragma unroll
            for (int np = 0; np < 2; ++np) {
                int nn = np * 2 + (lane >> 4);
                int rW = wn * 32 + nn * 8 + (lane & 7);
                unsigned wAddr = bW + (unsigned)(rW * 64)
                    + ((unsigned)((j * 2 + ((lane >> 3) & 1)) ^ ((rW >> 1) & 3)) << 4);
                ldsm4(WH[np*2][0], WH[np*2][1], WH[np*2+1][0], WH[np*2+1][1], wAddr);
                ldsm4(WL[np*2][0], WL[np*2][1], WL[np*2+1][0], WL[np*2+1][1],
                      wAddr + 8192u);
            }
            if (j == 1) {
                __syncthreads();     // all threads done reading this buffer
                if (tid == 0 && i + NBUF < nU) issue(i + NBUF);
            }
            // Term-outer MMA: 8 independent accumulators between reuses
            #pragma unroll
            for (int m = 0; m < 2; ++m)
                #pragma unroll
                for (int n = 0; n < 4; ++n)
                    mma16816(acc[m][n], AH[m], WH[n]);
            #pragma unroll
            for (int m = 0; m < 2; ++m)
                #pragma unroll
                for (int n = 0; n < 4; ++n)
                    mma16816(acc[m][n], AL[m], WH[n]);
            #pragma unroll
            for (int m = 0; m < 2; ++m)
                #pragma unroll
                for (int n = 0; n < 4; ++n)
                    mma16816(acc[m][n], AH[m], WL[n]);
        }
    }

    // Epilogue: D fragments -> pslot[b][c]
    #pragma unroll
    for (int m = 0; m < 2; ++m)
        #pragma unroll
        for (int n = 0; n < 4; ++n) {
            int b = wm * 32 + m * 16 + (lane >> 2);
            int c = wn * 32 + n * 8 + (lane & 3) * 2;
            *(float2*)(pslot + (size_t)b * 128 + c) =
                make_float2(acc[m][n][0], acc[m][n][1]);
            *(float2*)(pslot + (size_t)(b + 8) * 128 + c) =
                make_float2(acc[m][n][2], acc[m][n][3]);
        }
}

// ---------------------------------------------------------------------------
// Main persistent kernel: per step ONE merged gemm phase (gemm0(t) and
// gemm1(t-1) are independent) + ONE cell phase. 2 grid bars per step.
//   s0: L0 units [0,25)                    -> part0 slot0
//   s1: L0 units [25,36) -> part0 slot1;  L1 units [0,14)  -> part1 slot0
//   s2: L1 units [14,39)                   -> part1 slot1
//   s3: L1 units [39,64)                   -> part1 slot2
// ---------------------------------------------------------------------------
__global__ __launch_bounds__(NTHR, 1) void lstm_mma_kernel(
    const float* __restrict__ b_ih0, const float* __restrict__ b_hh0,
    const float* __restrict__ b_ih1, const float* __restrict__ b_hh1,
    const float* __restrict__ Wd,    const float* __restrict__ bd,
    float* __restrict__ out)
{
    extern __shared__ __align__(1024) unsigned char dsmem[];
    const unsigned sb = smem_u32(dsmem);
    const int tid  = threadIdx.x;
    const int cta  = blockIdx.x;
    const int tile = cta & 31;
    const int s    = cta >> 5;

    if (tid == 0) {
        #pragma unroll
        for (int i = 0; i < NBUF; ++i) mbar_init(sb + i * 8u, 1u);
        fence_async();
    }
    __syncthreads();

    unsigned ph[NBUF] = {0, 0, 0, 0};

    const unsigned char* w0 = g_W0t + (size_t)tile * NU0 * TILE16K;
    const unsigned char* w1 = g_W1t + (size_t)tile * 64u * TILE16K;
    float* p0s0 = g_part0 + ((size_t)(0 * 32 + tile) << 14);
    float* p0s1 = g_part0 + ((size_t)(1 * 32 + tile) << 14);
    float* p1s0 = g_part1 + ((size_t)(0 * 32 + tile) << 14);
    float* p1s1 = g_part1 + ((size_t)(1 * 32 + tile) << 14);
    float* p1s2 = g_part1 + ((size_t)(2 * 32 + tile) << 14);

    for (int t = 0; t <= TQ; ++t) {
        // ---- G phase: gemm0(t) [if t<TQ] and gemm1(t-1) [if t>0]
        const unsigned char* xt = g_xt + (size_t)t * 4 * TILE16K;
        if (s == 0) {
            if (t < TQ)
                gemm_seg(xt, 4, g_h0t, w0, 0, 25, p0s0, sb, ph);
        } else if (s == 1) {
            if (t < TQ)
                gemm_seg(xt, 4, g_h0t, w0, 25, 11, p0s1, sb, ph);
            if (t > 0)
                gemm_seg(g_h0t, 32, g_h1t, w1, 0, 14, p1s0, sb, ph);
        } else if (s == 2) {
            if (t > 0)
                gemm_seg(g_h0t, 32, g_h1t, w1, 14, 25, p1s1, sb, ph);
        } else {
            if (t > 0)
                gemm_seg(g_h0t, 32, g_h1t, w1, 39, 25, p1s2, sb, ph);
        }
        grid_bar();

        // ---- C phase: cell0(t) [if t<TQ] and cell1(t-1) [if t>0]
        if (t < TQ) {
            #pragma unroll
            for (int it = 0; it < (BQ * HQ) / (NCTA * NTHR); ++it)
                cell_slice<2>(it, g_c0, g_h0t, nullptr, g_part0, b_ih0, b_hh0);
        }
        if (t > 0) {
            float* hf = (t == TQ) ? g_h1f : nullptr;
            #pragma unroll
            for (int it = 0; it < (BQ * HQ) / (NCTA * NTHR); ++it)
                cell_slice<3>(it, g_c1, g_h1t, hf, g_part1, b_ih1, b_hh1);
        }
        grid_bar();
    }

    // Dense head: CTA b computes out[b][0..1] from fp32 h1
    {
        float* red = (float*)dsmem;
        const int b = cta;
        const int lane = tid & 31;
        const int wid  = tid >> 5;
        float s0 = 0.f, s1 = 0.f;
        for (int n = tid; n < HQ; n += NTHR) {
            float hv = g_h1f[(size_t)b * HQ + n];
            s0 += hv * Wd[n];
            s1 += hv * Wd[HQ + n];
        }
        #pragma unroll
        for (int off = 16; off > 0; off >>= 1) {
            s0 += __shfl_down_sync(0xffffffffu, s0, off);
            s1 += __shfl_down_sync(0xffffffffu, s1, off);
        }
        __syncthreads();
        if (lane == 0) { red[wid] = s0; red[16 + wid] = s1; }
        __syncthreads();
        if (tid == 0) {
            float a0 = 0.f, a1 = 0.f;
            #pragma unroll
            for (int w = 0; w < NTHR / 32; ++w) { a0 += red[w]; a1 += red[16 + w]; }
            out[b * 2 + 0] = tanhf(a0 + bd[0]);
            out[b * 2 + 1] = tanhf(a1 + bd[1]);
        }
    }
}

// ---------------------------------------------------------------------------
// Launch: 4 graph nodes
// ---------------------------------------------------------------------------
extern "C" void kernel_launch(void* const* d_in, const int* in_sizes, int n_in,
                              void* d_out, int out_size)
{
    const float* x     = (const float*)d_in[0];
    const float* W_ih0 = (const float*)d_in[1];
    const float* W_hh0 = (const float*)d_in[2];
    const float* b_ih0 = (const float*)d_in[3];
    const float* b_hh0 = (const float*)d_in[4];
    const float* W_ih1 = (const float*)d_in[5];
    const float* W_hh1 = (const float*)d_in[6];
    const float* b_ih1 = (const float*)d_in[7];
    const float* b_hh1 = (const float*)d_in[8];
    const float* Wd    = (const float*)d_in[9];
    const float* bd    = (const float*)d_in[10];
    float* out = (float*)d_out;

    const int smem_bytes = 1024 + NBUF * (int)STAGEB;   // 132096
    cudaFuncSetAttribute(lstm_mma_kernel,
                         cudaFuncAttributeMaxDynamicSharedMemorySize, smem_bytes);

    init_state_kernel<<<(32 * 16384 / 4 + 255) / 256, 256>>>();
    init_x_kernel<<<(BQ * TQ * INQ + 255) / 256, 256>>>(x);
    init_w_kernel<<<2048, 256>>>(W_ih0, W_hh0, W_ih1, W_hh1);

    lstm_mma_kernel<<<NCTA, NTHR, smem_bytes>>>(
        b_ih0, b_hh0, b_ih1, b_hh1, Wd, bd, out);
}